// round 15
// baseline (speedup 1.0000x reference)
#include <cuda_runtime.h>
#include <cuda_fp16.h>
#include <cstdint>

// ---------------------------------------------------------------------------
// GaborSelfAttention: ONE 2-D-windowed fp16 HMMA GEMM, cp.async.bulk stages.
//   out[ij,(b,f)] = sum_{h,kl} P[ij,h*1024+kl] * Y[(h,kl),(b,f)]
//   Y[(h,kl),(b,f)] = sum_e X[b,kl,e] * fc_w[f, e*8+h]
// M-tile = 32 rows (4i x 8j); K-support = 8h x 12k x 16l = 1536 (uniform).
// A pre-tiled+preswizzled (1 bulk 4KB/stage); B in 4 l-window copies,
// row-preswizzled (1 bulk 32KB/stage).  Split-K over heads (2 halves),
// red.global.add epilogue into pre-zeroed out; bias applied by half 0.
// ---------------------------------------------------------------------------

__device__ float  g_tab[8][420];            // exa[23]@0, eyb[63]@23, exy[331]@86
__device__ __half g_W2h[8 * 64 * 64];       // W2t[h][f][e]
__device__ __align__(1024) __half g_Xh[32 * 1024 * 64];        // 4 MB
__device__ __align__(1024) __half g_At[32 * 24 * 32 * 64];     // 3 MB  A tiled
__device__ __align__(1024) __half g_B2[4 * 8 * 8 * 2048 * 64]; // 64 MB B copies

// ------------------------------ PTX helpers -------------------------------
__device__ __forceinline__ uint32_t s2u(const void* p) {
    uint32_t a;
    asm("{ .reg .u64 t; cvta.to.shared.u64 t, %1; cvt.u32.u64 %0, t; }"
        : "=r"(a) : "l"(p));
    return a;
}
__device__ __forceinline__ void cpa16(uint32_t dst, const void* src) {
    asm volatile("cp.async.cg.shared.global [%0], [%1], 16;" :: "r"(dst), "l"(src));
}
__device__ __forceinline__ void cpa_commit() {
    asm volatile("cp.async.commit_group;" ::: "memory");
}
template <int N> __device__ __forceinline__ void cpa_wait() {
    asm volatile("cp.async.wait_group %0;" :: "n"(N) : "memory");
}
__device__ __forceinline__ void bulk_g2s(uint32_t dst, const void* src,
                                         uint32_t bytes, uint32_t mbar) {
    asm volatile(
        "cp.async.bulk.shared::cluster.global.mbarrier::complete_tx::bytes "
        "[%0], [%1], %2, [%3];"
        :: "r"(dst), "l"(src), "r"(bytes), "r"(mbar) : "memory");
}
__device__ __forceinline__ void bulk_s2g(void* gdst, uint32_t ssrc, uint32_t bytes) {
    asm volatile(
        "cp.async.bulk.global.shared::cta.bulk_group [%0], [%1], %2;"
        :: "l"(gdst), "r"(ssrc), "r"(bytes) : "memory");
}
#define TMA_S_COMMIT() asm volatile("cp.async.bulk.commit_group;" ::: "memory")
#define TMA_S_WAIT0()  asm volatile("cp.async.bulk.wait_group 0;" ::: "memory")
#define TMA_S_WAIT1()  asm volatile("cp.async.bulk.wait_group 1;" ::: "memory")
#define MBINIT(a, c) \
    asm volatile("mbarrier.init.shared.b64 [%0], %1;" :: "r"(a), "r"(c) : "memory")
#define MBEXPECT(a, n) \
    asm volatile("mbarrier.arrive.expect_tx.shared.b64 _, [%0], %1;" \
                 :: "r"(a), "r"(n) : "memory")
#define MBWAIT(addr, phw) do {                                                   \
    uint32_t _m = (addr), _p = (phw), _d;                                        \
    asm volatile("{\n\t.reg .pred p;\n\t"                                        \
        "mbarrier.try_wait.parity.acquire.cta.shared::cta.b64 p, [%1], %2;\n\t"  \
        "selp.b32 %0,1,0,p;\n\t}"                                                \
        : "=r"(_d) : "r"(_m), "r"(_p) : "memory");                               \
    if (!_d) {                                                                   \
        asm volatile("{\n\t.reg .pred P1;\n\t"                                   \
            "WL%=:\n\t"                                                          \
            "mbarrier.try_wait.parity.acquire.cta.shared::cta.b64 P1, [%0], %1, 0x989680;\n\t" \
            "@P1 bra.uni WD%=;\n\t"                                              \
            "bra.uni WL%=;\n\t"                                                  \
            "WD%=:\n\t}"                                                         \
            :: "r"(_m), "r"(_p) : "memory");                                     \
    }                                                                            \
} while (0)
__device__ __forceinline__ void mma16816(float c[4], const uint32_t a[4],
                                         const uint32_t b[2]) {
    asm volatile(
        "mma.sync.aligned.m16n8k16.row.col.f32.f16.f16.f32 "
        "{%0,%1,%2,%3}, {%4,%5,%6,%7}, {%8,%9}, {%0,%1,%2,%3};"
        : "+f"(c[0]), "+f"(c[1]), "+f"(c[2]), "+f"(c[3])
        : "r"(a[0]), "r"(a[1]), "r"(a[2]), "r"(a[3]), "r"(b[0]), "r"(b[1]));
}
__device__ __forceinline__ void ldm4(uint32_t r[4], uint32_t a) {
    asm volatile("ldmatrix.sync.aligned.m8n8.x4.shared.b16 {%0,%1,%2,%3}, [%4];"
        : "=r"(r[0]), "=r"(r[1]), "=r"(r[2]), "=r"(r[3]) : "r"(a));
}
__device__ __forceinline__ void redadd(float* p, float v) {
    asm volatile("red.global.add.f32 [%0], %1;" :: "l"(p), "f"(v) : "memory");
}
__device__ __forceinline__ uint32_t swz(uint32_t o) { return o ^ ((o >> 3) & 0x70); }

// ---------------------------------------------------------------------------
// Fused prep: blocks [0,1024) X->fp16; [1024,1152) fc_w transform;
// [1152,1160) per-head tables.
// ---------------------------------------------------------------------------
__global__ __launch_bounds__(256) void k_prep(const float* __restrict__ X,
                                              const float* __restrict__ fc_w,
                                              const float* __restrict__ centers,
                                              const float* __restrict__ spreads) {
    const int bx = blockIdx.x, tid = threadIdx.x;
    if (bx < 1024) {
        int i = bx * 256 + tid;
        const float4* src = (const float4*)X + (size_t)i * 2;
        float4 v0 = src[0], v1 = src[1];
        __half2 a = __floats2half2_rn(v0.x, v0.y);
        __half2 b = __floats2half2_rn(v0.z, v0.w);
        __half2 c = __floats2half2_rn(v1.x, v1.y);
        __half2 d = __floats2half2_rn(v1.z, v1.w);
        *(uint4*)&g_Xh[(size_t)i * 8] =
            make_uint4(*(uint32_t*)&a, *(uint32_t*)&b, *(uint32_t*)&c, *(uint32_t*)&d);
    } else if (bx < 1152) {
        int idx = (bx - 1024) * 256 + tid;    // 32768
        int h = idx >> 12, f = (idx >> 6) & 63, e = idx & 63;
        g_W2h[idx] = __float2half_rn(fc_w[f*512 + e*8 + h]);
    } else {
        const int h = bx - 1152;
        float s00 = spreads[h*4+0], s01 = spreads[h*4+1];
        float s10 = spreads[h*4+2], s11 = spreads[h*4+3];
        float a  = s00*s00 + s01*s01;
        float bb = s00*s10 + s01*s11;
        float c  = s10*s10 + s11*s11;
        float m1 = centers[h*2+0], m2 = centers[h*2+1];
        float u0 = a*m1 + bb*m2;
        float u1 = c*m2 + bb*m1;
        float u2 = -0.5f*a;
        float u3 = -0.5f*c;
        float u4 = -bb;
        for (int t = tid; t < 417; t += 256) {
            float v;
            if (t < 23)      { float dx = (float)(t - 11);       v = expf((u0 + u2*dx)*dx); }
            else if (t < 86) { float dy = (float)(t - 23 - 31);  v = expf((u1 + u3*dy)*dy); }
            else             { float m  = (float)(t - 86 - 165); v = expf(u4*m); }
            g_tab[h][t] = v;
        }
    }
}

// zero the output buffer (for red.add epilogue)
__global__ __launch_bounds__(256) void k_zero(float* __restrict__ out) {
    int i = blockIdx.x * 256 + threadIdx.x;      // 524288 uint4
    ((uint4*)out)[i] = make_uint4(0u, 0u, 0u, 0u);
}

// ---------------------------------------------------------------------------
// Y^T via HMMA, M = f, one block per (b,h), 8 kl-chunks of 128 pipelined:
//   C[64 f x 128 kl] = W[64 f x 64 e] @ X[128 kl x 64 e]^T
// W fragments hoisted to registers; staging double-buffered; async bulk S2G.
// smem: W 8K @0 | X 2x16K @8192 | staging 2x32K @40960  = 104 KB dynamic.
// ---------------------------------------------------------------------------
#define Y2_SMEM 106496
__global__ __launch_bounds__(256) void k_y2() {
    extern __shared__ __align__(1024) char dsm[];
    const uint32_t sb = s2u(dsm);
    const uint32_t ws = sb;
    const int tid = threadIdx.x, l = tid & 31, wid = tid >> 5;
    const int bx = blockIdx.x;           // 0..255
    const int b = bx >> 3, h = bx & 7;
    const int warp_m = wid >> 2, warp_n = wid & 3;

    auto loadX = [&](int c) {
        uint32_t xs = sb + 8192 + (c & 1) * 16384;
        const __half* Xg = g_Xh + ((size_t)b*1024 + c*128) * 64;
#pragma unroll
        for (int q = 0; q < 4; q++) {
            int idx = q*256 + tid;
            int r = idx >> 3, cc = idx & 7;
            cpa16(xs + swz(r*128 + cc*16), Xg + (size_t)r*64 + cc*8);
        }
        cpa_commit();
    };

    {   // group 0: W + X0
        const __half* Wg = g_W2h + h*4096;
#pragma unroll
        for (int q = 0; q < 2; q++) {
            int idx = q*256 + tid;
            int r = idx >> 3, cc = idx & 7;
            cpa16(ws + swz(r*128 + cc*16), Wg + (size_t)r*64 + cc*8);
        }
        loadX(0);
    }
    loadX(1);

    const int lm_r = (l & 7) + ((l >> 3) & 1) * 8;
    const int lm_c = l >> 4;
    const int r8 = l >> 2, kq = (l & 3) * 2;
    const int lg0s[4] = {0, 4, 12, 16};

    uint32_t aw[4][2][4];                 // W fragments [ks][mi][4]

    for (int ck = 0; ck < 8; ck++) {
        cpa_wait<1>();
        __syncthreads();
        if (ck == 0) {
#pragma unroll
            for (int ks = 0; ks < 4; ks++) {
                const int ch = 2*ks + lm_c;
#pragma unroll
                for (int mi = 0; mi < 2; mi++)
                    ldm4(aw[ks][mi], ws + swz((warp_m*32 + mi*16 + lm_r)*128 + ch*16));
            }
        }

        const uint32_t xs = sb + 8192 + (ck & 1) * 16384;
        float acc[2][4][4];
#pragma unroll
        for (int mi = 0; mi < 2; mi++)
#pragma unroll
            for (int ni = 0; ni < 4; ni++)
#pragma unroll
                for (int q = 0; q < 4; q++) acc[mi][ni][q] = 0.f;

#pragma unroll
        for (int ks = 0; ks < 4; ks++) {
            const int ch = 2*ks + lm_c;
            uint32_t bq[2][4];
#pragma unroll
            for (int nb = 0; nb < 2; nb++)
                ldm4(bq[nb], xs + swz((warp_n*32 + nb*16 + lm_r)*128 + ch*16));
#pragma unroll
            for (int mi = 0; mi < 2; mi++)
#pragma unroll
                for (int ni = 0; ni < 4; ni++) {
                    uint32_t bb[2] = {bq[ni>>1][ni&1], bq[ni>>1][(ni&1)+2]};
                    mma16816(acc[mi][ni], aw[ks][mi], bb);
                }
        }

        // staging[ck&1] reusable once bulk(ck-2) finished
        if (tid < 4) TMA_S_WAIT1();
        __syncthreads();

        const uint32_t st = sb + 40960 + (ck & 1) * 32768;
#pragma unroll
        for (int mi = 0; mi < 2; mi++)
#pragma unroll
            for (int rh = 0; rh < 2; rh++) {
                const int f = warp_m*32 + mi*16 + r8 + rh*8;
                const int xr = f & 7;
                const uint32_t frow = st + f*128;
#pragma unroll
                for (int ni = 0; ni < 4; ni++) {
                    const int ll = ni*8 + kq;
                    __half2 hv = __floats2half2_rn(acc[mi][ni][rh*2],
                                                   acc[mi][ni][rh*2 + 1]);
                    const uint32_t hvu = *(uint32_t*)&hv;
#pragma unroll
                    for (int c = 0; c < 4; c++) {
                        const int lg = lg0s[c];
                        if (ll >= lg && ll < lg + 16) {
                            const int colc = warp_n*16 + (ll - lg);   // 0..63
                            const uint32_t addr = frow + c*8192
                                + ((uint32_t)((colc >> 3) ^ xr) << 4)
                                + ((uint32_t)(colc & 7) << 1);
                            asm volatile("st.shared.b32 [%0], %1;"
                                         :: "r"(addr), "r"(hvu));
                        }
                    }
                }
            }
        __syncthreads();

        if (tid < 4) {
            asm volatile("fence.proxy.async.shared::cta;" ::: "memory");
            __half* gdst = g_B2 + ((((size_t)tid*8 + h)*8 + ck)*2048
                                   + (size_t)b*64) * 64;
            bulk_s2g(gdst, st + tid*8192, 8192);
            TMA_S_COMMIT();
        }
        if (ck < 6) loadX(ck + 2); else cpa_commit();
    }
    if (tid < 4) TMA_S_WAIT0();
}

// ---------------------------------------------------------------------------
// P on the rect support, written tiled+preswizzled into g_At[bm][st][r][col].
// Per (ij,h): k in [kg0,kg0+12), l in [lg0,lg0+16);
// kg0 = clamp((i&~3)-4,0,20), lg0 = clamp((j&~7)-4,0,16).
// grid = 1024 (ij), 8 warps = 8 heads; lane (0..23) = one 8-half chunk.
// ---------------------------------------------------------------------------
__global__ __launch_bounds__(256) void k_probs() {
    __shared__ float tab[8][420];
    const int tid = threadIdx.x, l = tid & 31, wid = tid >> 5;
#pragma unroll
    for (int q = 0; q < 14; q++) {
        int idx = q*256 + tid;            // 3360 floats
        if (idx < 3360) ((float*)tab)[idx] = ((const float*)g_tab)[idx];
    }
    __syncthreads();

    const int ij = blockIdx.x;
    const int i = ij >> 5, j = ij & 31;
    const int i0 = i & ~3, j0 = j & ~7;
    const int kg0 = min(max(i0 - 4, 0), 20);
    const int lg0 = min(max(j0 - 4, 0), 16);
    const float* th = tab[wid];

    const bool act = (l < 24);
    const int kk = l >> 1;                 // 0..11
    const int llo = (l & 1) * 8;
    float p[8];
    float s = 0.f;
    if (act) {
        const int dx = kg0 + kk - i;
        const float ex = th[dx + 11];
#pragma unroll
        for (int q = 0; q < 8; q++) {
            int dy = lg0 + llo + q - j;
            p[q] = ex * th[23 + dy + 31] * th[86 + dx*dy + 165];
            s += p[q];
        }
    }
#pragma unroll
    for (int o = 16; o > 0; o >>= 1) s += __shfl_xor_sync(0xffffffffu, s, o);
    const float inv = 1.0f / s;

    if (act) {
        const int bm = (i >> 2) * 4 + (j >> 3);
        const int r  = (i & 3) * 8 + (j & 7);
        const int st = wid * 3 + (kk >> 2);
        const int chunk = ((kk & 3) * 2 + (l & 1)) ^ (r & 7);
        __half* dst = g_At + (((size_t)bm*24 + st)*32 + r)*64 + chunk*8;
        __half2 h0 = __floats2half2_rn(p[0]*inv, p[1]*inv);
        __half2 h1 = __floats2half2_rn(p[2]*inv, p[3]*inv);
        __half2 h2 = __floats2half2_rn(p[4]*inv, p[5]*inv);
        __half2 h3 = __floats2half2_rn(p[6]*inv, p[7]*inv);
        *(uint4*)dst = make_uint4(*(uint32_t*)&h0, *(uint32_t*)&h1,
                                  *(uint32_t*)&h2, *(uint32_t*)&h3);
    }
}

// ---------------------------------------------------------------------------
// Main GEMM: BM=32 (4i x 8j), BN=256, split-K over heads (halves of 4).
// 12 stages of 64 cols (1h, 4k, 16l).  grid (8 bn, 64 = 32 bm x 2 half),
// 256 threads (2m x 4n warps).  Stage: A 4KB + B 32KB; 3-stage pipeline.
// Epilogue: red.global.add into pre-zeroed out (+bias from half 0, all rows).
// ---------------------------------------------------------------------------
#define GSTG 36864
#define GSMEM (3*GSTG + 64)
__global__ __launch_bounds__(256, 1) void k_gemm(const float* __restrict__ fc_b,
                                                 float* __restrict__ out) {
    extern __shared__ __align__(1024) char sm[];
    const uint32_t sbase = s2u(sm);
    const uint32_t mb = sbase + 3*GSTG;
    const int tid = threadIdx.x, l = tid & 31, wid = tid >> 5;
    const int warp_m = wid >> 2, warp_n = wid & 3;
    const int bn = blockIdx.x;
    const int bm = blockIdx.y & 31, half = blockIdx.y >> 5;

    const int i0 = (bm >> 2) * 4, j0 = (bm & 3) * 8;
    const int kg0 = min(max(i0 - 4, 0), 20);
    const int lg0 = min(max(j0 - 4, 0), 16);
    const int cpy = (lg0 == 0) ? 0 : (lg0 == 4) ? 1 : (lg0 == 12) ? 2 : 3;
    const int kgbase = kg0 >> 2;

    if (tid == 0) {
#pragma unroll
        for (int q = 0; q < 3; q++) MBINIT(mb + q*8, 1);
    }
    asm volatile("fence.proxy.async.shared::cta;" ::: "memory");
    __syncthreads();

    // A stages for this half: global stage index = half*12 + t
    const __half* At0 = g_At + (size_t)bm * 24 * 2048 + (size_t)half * 12 * 2048;

    auto load_stage = [&](int buf, int t) {
        if (tid == 0) {
            const uint32_t stg = sbase + buf * GSTG;
            const uint32_t mbar = mb + buf * 8;
            const int hh = half*4 + t / 3, kgi = t - (t / 3) * 3;
            MBEXPECT(mbar, 36864);
            bulk_g2s(stg, At0 + (size_t)t * 2048, 4096, mbar);
            const __half* Bsrc = g_B2 +
                ((((size_t)cpy*8 + hh)*8 + (kgbase + kgi))*2048
                 + (size_t)bn*256) * 64;
            bulk_g2s(stg + 4096, Bsrc, 32768, mbar);
        }
    };

    float acc[8][4];
#pragma unroll
    for (int ni = 0; ni < 8; ni++)
#pragma unroll
        for (int q = 0; q < 4; q++) acc[ni][q] = 0.f;

    load_stage(0, 0); load_stage(1, 1); load_stage(2, 2);

    const int lm_r = (l & 7) + ((l >> 3) & 1) * 8;
    const int lm_c = l >> 4;

    for (int t = 0; t < 12; t++) {
        const int bt = t % 3;
        MBWAIT(mb + bt*8, (t/3) & 1);

        const uint32_t Ab = sbase + bt*GSTG, Bb = Ab + 4096;
#pragma unroll
        for (int ks = 0; ks < 4; ks++) {
            const int ch = 2*ks + lm_c;
            uint32_t a[4], bq[4][4];
            ldm4(a, Ab + swz((warp_m*16 + lm_r)*128 + ch*16));
#pragma unroll
            for (int nb = 0; nb < 4; nb++)
                ldm4(bq[nb], Bb + swz((warp_n*64 + nb*16 + lm_r)*128 + ch*16));
#pragma unroll
            for (int ni = 0; ni < 8; ni++) {
                uint32_t bb[2] = {bq[ni>>1][ni&1], bq[ni>>1][(ni&1)+2]};
                mma16816(acc[ni], a, bb);
            }
        }
        __syncthreads();                       // all warps done with buffer bt
        if (t + 3 < 12) load_stage(bt, t + 3);
    }

    // epilogue: col = bn*256 + warp_n*64 + ni*8 + kq -> bidx = bn*4+warp_n
    const int r8 = l >> 2, kq = (l & 3) * 2;
    const int bidx = bn * 4 + warp_n;
    const int m0 = warp_m * 16 + r8;           // rows m0, m0+8
    const int ijA = (i0 + (m0 >> 3)) * 32 + j0 + (m0 & 7);
    const int mB = m0 + 8;
    const int ijB = (i0 + (mB >> 3)) * 32 + j0 + (mB & 7);

    float* outb = out + (size_t)bidx * 65536;
#pragma unroll
    for (int ni = 0; ni < 8; ni++) {
        int f = ni*8 + kq;
        float b0 = 0.f, b1 = 0.f;
        if (half == 0) { b0 = fc_b[f]; b1 = fc_b[f+1]; }
        redadd(&outb[(size_t)ijA * 64 + f],     acc[ni][0] + b0);
        redadd(&outb[(size_t)ijA * 64 + f + 1], acc[ni][1] + b1);
        redadd(&outb[(size_t)ijB * 64 + f],     acc[ni][2] + b0);
        redadd(&outb[(size_t)ijB * 64 + f + 1], acc[ni][3] + b1);
    }
}

// ---------------------------------------------------------------------------
extern "C" void kernel_launch(void* const* d_in, const int* in_sizes, int n_in,
                              void* d_out, int out_size) {
    const float* X       = (const float*)d_in[0];
    const float* centers = (const float*)d_in[2];
    const float* spreads = (const float*)d_in[3];
    const float* fc_w    = (const float*)d_in[4];
    const float* fc_b    = (const float*)d_in[5];
    float* out = (float*)d_out;

    cudaFuncSetAttribute(k_y2, cudaFuncAttributeMaxDynamicSharedMemorySize, Y2_SMEM);
    cudaFuncSetAttribute(k_gemm, cudaFuncAttributeMaxDynamicSharedMemorySize, GSMEM);

    k_prep<<<1160, 256>>>(X, fc_w, centers, spreads);
    k_zero<<<2048, 256>>>(out);
    k_probs<<<1024, 256>>>();
    k_y2<<<256, 256, Y2_SMEM>>>();
    dim3 gg(8, 64);
    k_gemm<<<gg, 256, GSMEM>>>(fc_b, out);
}

// round 16
// speedup vs baseline: 1.2213x; 1.2213x over previous
#include <cuda_runtime.h>
#include <cuda_fp16.h>
#include <cstdint>

// ---------------------------------------------------------------------------
// GaborSelfAttention: ONE 2-D-windowed fp16 HMMA GEMM, cp.async.bulk stages.
//   out[ij,(b,f)] = sum_{h,kl} P[ij,h*1024+kl] * Y[(h,kl),(b,f)]
//   Y[(h,kl),(b,f)] = sum_e X[b,kl,e] * fc_w[f, e*8+h]
// M-tile = 32 rows (4i x 8j); K-support = 8h x 12k x 16l = 1536 (uniform).
// A pre-tiled+preswizzled (1 bulk 4KB/stage); B in 4 l-window copies,
// row-preswizzled (1 bulk 32KB/stage).  k_mid merges Y^T build + probs.
// ---------------------------------------------------------------------------

__device__ float  g_tab[8][420];            // exa[23]@0, eyb[63]@23, exy[331]@86
__device__ __half g_W2h[8 * 64 * 64];       // W2t[h][f][e]
__device__ __align__(1024) __half g_Xh[32 * 1024 * 64];        // 4 MB
__device__ __align__(1024) __half g_At[32 * 24 * 32 * 64];     // 3 MB  A tiled
__device__ __align__(1024) __half g_B2[4 * 8 * 8 * 2048 * 64]; // 64 MB B copies

// ------------------------------ PTX helpers -------------------------------
__device__ __forceinline__ uint32_t s2u(const void* p) {
    uint32_t a;
    asm("{ .reg .u64 t; cvta.to.shared.u64 t, %1; cvt.u32.u64 %0, t; }"
        : "=r"(a) : "l"(p));
    return a;
}
__device__ __forceinline__ void cpa16(uint32_t dst, const void* src) {
    asm volatile("cp.async.cg.shared.global [%0], [%1], 16;" :: "r"(dst), "l"(src));
}
__device__ __forceinline__ void cpa_commit() {
    asm volatile("cp.async.commit_group;" ::: "memory");
}
template <int N> __device__ __forceinline__ void cpa_wait() {
    asm volatile("cp.async.wait_group %0;" :: "n"(N) : "memory");
}
__device__ __forceinline__ void bulk_g2s(uint32_t dst, const void* src,
                                         uint32_t bytes, uint32_t mbar) {
    asm volatile(
        "cp.async.bulk.shared::cluster.global.mbarrier::complete_tx::bytes "
        "[%0], [%1], %2, [%3];"
        :: "r"(dst), "l"(src), "r"(bytes), "r"(mbar) : "memory");
}
__device__ __forceinline__ void bulk_s2g(void* gdst, uint32_t ssrc, uint32_t bytes) {
    asm volatile(
        "cp.async.bulk.global.shared::cta.bulk_group [%0], [%1], %2;"
        :: "l"(gdst), "r"(ssrc), "r"(bytes) : "memory");
}
#define TMA_S_COMMIT() asm volatile("cp.async.bulk.commit_group;" ::: "memory")
#define TMA_S_WAIT0()  asm volatile("cp.async.bulk.wait_group 0;" ::: "memory")
#define TMA_S_WAIT1()  asm volatile("cp.async.bulk.wait_group 1;" ::: "memory")
#define MBINIT(a, c) \
    asm volatile("mbarrier.init.shared.b64 [%0], %1;" :: "r"(a), "r"(c) : "memory")
#define MBEXPECT(a, n) \
    asm volatile("mbarrier.arrive.expect_tx.shared.b64 _, [%0], %1;" \
                 :: "r"(a), "r"(n) : "memory")
#define MBWAIT(addr, phw) do {                                                   \
    uint32_t _m = (addr), _p = (phw), _d;                                        \
    asm volatile("{\n\t.reg .pred p;\n\t"                                        \
        "mbarrier.try_wait.parity.acquire.cta.shared::cta.b64 p, [%1], %2;\n\t"  \
        "selp.b32 %0,1,0,p;\n\t}"                                                \
        : "=r"(_d) : "r"(_m), "r"(_p) : "memory");                               \
    if (!_d) {                                                                   \
        asm volatile("{\n\t.reg .pred P1;\n\t"                                   \
            "WL%=:\n\t"                                                          \
            "mbarrier.try_wait.parity.acquire.cta.shared::cta.b64 P1, [%0], %1, 0x989680;\n\t" \
            "@P1 bra.uni WD%=;\n\t"                                              \
            "bra.uni WL%=;\n\t"                                                  \
            "WD%=:\n\t}"                                                         \
            :: "r"(_m), "r"(_p) : "memory");                                     \
    }                                                                            \
} while (0)
__device__ __forceinline__ void mma16816(float c[4], const uint32_t a[4],
                                         const uint32_t b[2]) {
    asm volatile(
        "mma.sync.aligned.m16n8k16.row.col.f32.f16.f16.f32 "
        "{%0,%1,%2,%3}, {%4,%5,%6,%7}, {%8,%9}, {%0,%1,%2,%3};"
        : "+f"(c[0]), "+f"(c[1]), "+f"(c[2]), "+f"(c[3])
        : "r"(a[0]), "r"(a[1]), "r"(a[2]), "r"(a[3]), "r"(b[0]), "r"(b[1]));
}
__device__ __forceinline__ void ldm4(uint32_t r[4], uint32_t a) {
    asm volatile("ldmatrix.sync.aligned.m8n8.x4.shared.b16 {%0,%1,%2,%3}, [%4];"
        : "=r"(r[0]), "=r"(r[1]), "=r"(r[2]), "=r"(r[3]) : "r"(a));
}
__device__ __forceinline__ uint32_t swz(uint32_t o) { return o ^ ((o >> 3) & 0x70); }

// ---------------------------------------------------------------------------
// Fused prep: blocks [0,1024) X->fp16; [1024,1152) fc_w transform;
// [1152,1160) per-head tables.
// ---------------------------------------------------------------------------
__global__ __launch_bounds__(256) void k_prep(const float* __restrict__ X,
                                              const float* __restrict__ fc_w,
                                              const float* __restrict__ centers,
                                              const float* __restrict__ spreads) {
    const int bx = blockIdx.x, tid = threadIdx.x;
    if (bx < 1024) {
        int i = bx * 256 + tid;
        const float4* src = (const float4*)X + (size_t)i * 2;
        float4 v0 = src[0], v1 = src[1];
        __half2 a = __floats2half2_rn(v0.x, v0.y);
        __half2 b = __floats2half2_rn(v0.z, v0.w);
        __half2 c = __floats2half2_rn(v1.x, v1.y);
        __half2 d = __floats2half2_rn(v1.z, v1.w);
        *(uint4*)&g_Xh[(size_t)i * 8] =
            make_uint4(*(uint32_t*)&a, *(uint32_t*)&b, *(uint32_t*)&c, *(uint32_t*)&d);
    } else if (bx < 1152) {
        int idx = (bx - 1024) * 256 + tid;    // 32768
        int h = idx >> 12, f = (idx >> 6) & 63, e = idx & 63;
        g_W2h[idx] = __float2half_rn(fc_w[f*512 + e*8 + h]);
    } else {
        const int h = bx - 1152;
        float s00 = spreads[h*4+0], s01 = spreads[h*4+1];
        float s10 = spreads[h*4+2], s11 = spreads[h*4+3];
        float a  = s00*s00 + s01*s01;
        float bb = s00*s10 + s01*s11;
        float c  = s10*s10 + s11*s11;
        float m1 = centers[h*2+0], m2 = centers[h*2+1];
        float u0 = a*m1 + bb*m2;
        float u1 = c*m2 + bb*m1;
        float u2 = -0.5f*a;
        float u3 = -0.5f*c;
        float u4 = -bb;
        for (int t = tid; t < 417; t += 256) {
            float v;
            if (t < 23)      { float dx = (float)(t - 11);       v = expf((u0 + u2*dx)*dx); }
            else if (t < 86) { float dy = (float)(t - 23 - 31);  v = expf((u1 + u3*dy)*dy); }
            else             { float m  = (float)(t - 86 - 165); v = expf(u4*m); }
            g_tab[h][t] = v;
        }
    }
}

// ---------------------------------------------------------------------------
// k_mid: merged middle stage, block-range dispatch.
//   blocks [0,256):    Y^T build (one block per (b,h), 8 kl-chunks pipelined)
//   blocks [256,1280): probs on rect support -> g_At (one block per ij)
// dyn smem 104 KB (y2 layout: W 8K @0 | X 2x16K @8192 | staging 2x32K @40960;
// probs blocks reuse the first 13.4 KB as the table cache).
// ---------------------------------------------------------------------------
#define MID_SMEM 106496
__global__ __launch_bounds__(256) void k_mid() {
    extern __shared__ __align__(1024) char dsm[];
    const int tid = threadIdx.x, l = tid & 31, wid = tid >> 5;
    const int bx = blockIdx.x;

    if (bx < 256) {
        // ---------------- Y^T build ----------------
        const uint32_t sb = s2u(dsm);
        const uint32_t ws = sb;
        const int b = bx >> 3, h = bx & 7;
        const int warp_m = wid >> 2, warp_n = wid & 3;

        auto loadX = [&](int c) {
            uint32_t xs = sb + 8192 + (c & 1) * 16384;
            const __half* Xg = g_Xh + ((size_t)b*1024 + c*128) * 64;
#pragma unroll
            for (int q = 0; q < 4; q++) {
                int idx = q*256 + tid;
                int r = idx >> 3, cc = idx & 7;
                cpa16(xs + swz(r*128 + cc*16), Xg + (size_t)r*64 + cc*8);
            }
            cpa_commit();
        };

        {   // group 0: W + X0
            const __half* Wg = g_W2h + h*4096;
#pragma unroll
            for (int q = 0; q < 2; q++) {
                int idx = q*256 + tid;
                int r = idx >> 3, cc = idx & 7;
                cpa16(ws + swz(r*128 + cc*16), Wg + (size_t)r*64 + cc*8);
            }
            loadX(0);
        }
        loadX(1);

        const int lm_r = (l & 7) + ((l >> 3) & 1) * 8;
        const int lm_c = l >> 4;
        const int r8 = l >> 2, kq = (l & 3) * 2;
        const int lg0s[4] = {0, 4, 12, 16};

        uint32_t aw[4][2][4];                 // W fragments [ks][mi][4]

        for (int ck = 0; ck < 8; ck++) {
            cpa_wait<1>();
            __syncthreads();
            if (ck == 0) {
#pragma unroll
                for (int ks = 0; ks < 4; ks++) {
                    const int ch = 2*ks + lm_c;
#pragma unroll
                    for (int mi = 0; mi < 2; mi++)
                        ldm4(aw[ks][mi],
                             ws + swz((warp_m*32 + mi*16 + lm_r)*128 + ch*16));
                }
            }

            const uint32_t xs = sb + 8192 + (ck & 1) * 16384;
            float acc[2][4][4];
#pragma unroll
            for (int mi = 0; mi < 2; mi++)
#pragma unroll
                for (int ni = 0; ni < 4; ni++)
#pragma unroll
                    for (int q = 0; q < 4; q++) acc[mi][ni][q] = 0.f;

#pragma unroll
            for (int ks = 0; ks < 4; ks++) {
                const int ch = 2*ks + lm_c;
                uint32_t bq[2][4];
#pragma unroll
                for (int nb = 0; nb < 2; nb++)
                    ldm4(bq[nb], xs + swz((warp_n*32 + nb*16 + lm_r)*128 + ch*16));
#pragma unroll
                for (int mi = 0; mi < 2; mi++)
#pragma unroll
                    for (int ni = 0; ni < 4; ni++) {
                        uint32_t bb[2] = {bq[ni>>1][ni&1], bq[ni>>1][(ni&1)+2]};
                        mma16816(acc[mi][ni], aw[ks][mi], bb);
                    }
            }

            // staging[ck&1] reusable once bulk(ck-2) finished
            if (tid < 4) TMA_S_WAIT1();
            __syncthreads();

            const uint32_t st = sb + 40960 + (ck & 1) * 32768;
#pragma unroll
            for (int mi = 0; mi < 2; mi++)
#pragma unroll
                for (int rh = 0; rh < 2; rh++) {
                    const int f = warp_m*32 + mi*16 + r8 + rh*8;
                    const int xr = f & 7;
                    const uint32_t frow = st + f*128;
#pragma unroll
                    for (int ni = 0; ni < 4; ni++) {
                        const int ll = ni*8 + kq;
                        __half2 hv = __floats2half2_rn(acc[mi][ni][rh*2],
                                                       acc[mi][ni][rh*2 + 1]);
                        const uint32_t hvu = *(uint32_t*)&hv;
#pragma unroll
                        for (int c = 0; c < 4; c++) {
                            const int lg = lg0s[c];
                            if (ll >= lg && ll < lg + 16) {
                                const int colc = warp_n*16 + (ll - lg);   // 0..63
                                const uint32_t addr = frow + c*8192
                                    + ((uint32_t)((colc >> 3) ^ xr) << 4)
                                    + ((uint32_t)(colc & 7) << 1);
                                asm volatile("st.shared.b32 [%0], %1;"
                                             :: "r"(addr), "r"(hvu));
                            }
                        }
                    }
                }
            __syncthreads();

            if (tid < 4) {
                asm volatile("fence.proxy.async.shared::cta;" ::: "memory");
                __half* gdst = g_B2 + ((((size_t)tid*8 + h)*8 + ck)*2048
                                       + (size_t)b*64) * 64;
                bulk_s2g(gdst, st + tid*8192, 8192);
                TMA_S_COMMIT();
            }
            if (ck < 6) loadX(ck + 2); else cpa_commit();
        }
        if (tid < 4) TMA_S_WAIT0();
    } else {
        // ---------------- probs ----------------
        float* tab = (float*)dsm;             // [8][420]
#pragma unroll
        for (int q = 0; q < 14; q++) {
            int idx = q*256 + tid;            // 3360 floats
            if (idx < 3360) tab[idx] = ((const float*)g_tab)[idx];
        }
        __syncthreads();

        const int ij = bx - 256;
        const int i = ij >> 5, j = ij & 31;
        const int i0 = i & ~3, j0 = j & ~7;
        const int kg0 = min(max(i0 - 4, 0), 20);
        const int lg0 = min(max(j0 - 4, 0), 16);
        const float* th = tab + wid * 420;

        const bool act = (l < 24);
        const int kk = l >> 1;                 // 0..11
        const int llo = (l & 1) * 8;
        float p[8];
        float s = 0.f;
        if (act) {
            const int dx = kg0 + kk - i;
            const float ex = th[dx + 11];
#pragma unroll
            for (int q = 0; q < 8; q++) {
                int dy = lg0 + llo + q - j;
                p[q] = ex * th[23 + dy + 31] * th[86 + dx*dy + 165];
                s += p[q];
            }
        }
#pragma unroll
        for (int o = 16; o > 0; o >>= 1) s += __shfl_xor_sync(0xffffffffu, s, o);
        const float inv = 1.0f / s;

        if (act) {
            const int bm = (i >> 2) * 4 + (j >> 3);
            const int r  = (i & 3) * 8 + (j & 7);
            const int st = wid * 3 + (kk >> 2);
            const int chunk = ((kk & 3) * 2 + (l & 1)) ^ (r & 7);
            __half* dst = g_At + (((size_t)bm*24 + st)*32 + r)*64 + chunk*8;
            __half2 h0 = __floats2half2_rn(p[0]*inv, p[1]*inv);
            __half2 h1 = __floats2half2_rn(p[2]*inv, p[3]*inv);
            __half2 h2 = __floats2half2_rn(p[4]*inv, p[5]*inv);
            __half2 h3 = __floats2half2_rn(p[6]*inv, p[7]*inv);
            *(uint4*)dst = make_uint4(*(uint32_t*)&h0, *(uint32_t*)&h1,
                                      *(uint32_t*)&h2, *(uint32_t*)&h3);
        }
    }
}

// ---------------------------------------------------------------------------
// Main GEMM (R12): BM=32 (4i x 8j), BN=256, K = 1536 in 24 stages of 64 cols
// (1h, 4k, 16l).  grid (8 bn, 32 bm), 256 threads (2m x 4n warps).
// Stage: A 4KB (1 bulk) + B 32KB (1 bulk); 3-stage mbarrier pipeline.
// ---------------------------------------------------------------------------
#define GSTG 36864
#define GSMEM (3*GSTG + 64)
__global__ __launch_bounds__(256, 1) void k_gemm(const float* __restrict__ fc_b,
                                                 float* __restrict__ out) {
    extern __shared__ __align__(1024) char sm[];
    const uint32_t sbase = s2u(sm);
    const uint32_t mb = sbase + 3*GSTG;
    const int tid = threadIdx.x, l = tid & 31, wid = tid >> 5;
    const int warp_m = wid >> 2, warp_n = wid & 3;
    const int bn = blockIdx.x, bm = blockIdx.y;

    const int i0 = (bm >> 2) * 4, j0 = (bm & 3) * 8;
    const int kg0 = min(max(i0 - 4, 0), 20);
    const int lg0 = min(max(j0 - 4, 0), 16);
    const int cpy = (lg0 == 0) ? 0 : (lg0 == 4) ? 1 : (lg0 == 12) ? 2 : 3;
    const int kgbase = kg0 >> 2;

    if (tid == 0) {
#pragma unroll
        for (int q = 0; q < 3; q++) MBINIT(mb + q*8, 1);
    }
    asm volatile("fence.proxy.async.shared::cta;" ::: "memory");
    __syncthreads();

    const __half* At0 = g_At + (size_t)bm * 24 * 2048;

    auto load_stage = [&](int buf, int t) {
        if (tid == 0) {
            const uint32_t stg = sbase + buf * GSTG;
            const uint32_t mbar = mb + buf * 8;
            const int hh = t / 3, kgi = t - hh * 3;
            MBEXPECT(mbar, 36864);
            bulk_g2s(stg, At0 + (size_t)t * 2048, 4096, mbar);
            const __half* Bsrc = g_B2 +
                ((((size_t)cpy*8 + hh)*8 + (kgbase + kgi))*2048
                 + (size_t)bn*256) * 64;
            bulk_g2s(stg + 4096, Bsrc, 32768, mbar);
        }
    };

    float acc[8][4];
#pragma unroll
    for (int ni = 0; ni < 8; ni++)
#pragma unroll
        for (int q = 0; q < 4; q++) acc[ni][q] = 0.f;

    load_stage(0, 0); load_stage(1, 1); load_stage(2, 2);

    const int lm_r = (l & 7) + ((l >> 3) & 1) * 8;
    const int lm_c = l >> 4;

    for (int t = 0; t < 24; t++) {
        const int bt = t % 3;
        MBWAIT(mb + bt*8, (t/3) & 1);

        const uint32_t Ab = sbase + bt*GSTG, Bb = Ab + 4096;
#pragma unroll
        for (int ks = 0; ks < 4; ks++) {
            const int ch = 2*ks + lm_c;
            uint32_t a[4], bq[4][4];
            ldm4(a, Ab + swz((warp_m*16 + lm_r)*128 + ch*16));
#pragma unroll
            for (int nb = 0; nb < 4; nb++)
                ldm4(bq[nb], Bb + swz((warp_n*64 + nb*16 + lm_r)*128 + ch*16));
#pragma unroll
            for (int ni = 0; ni < 8; ni++) {
                uint32_t bb[2] = {bq[ni>>1][ni&1], bq[ni>>1][(ni&1)+2]};
                mma16816(acc[ni], a, bb);
            }
        }
        __syncthreads();                       // all warps done with buffer bt
        if (t + 3 < 24) load_stage(bt, t + 3);
    }

    // epilogue: col = bn*256 + warp_n*64 + ni*8 + kq -> bidx = bn*4+warp_n
    const int r8 = l >> 2, kq = (l & 3) * 2;
    const int bidx = bn * 4 + warp_n;
    const int m0 = warp_m * 16 + r8;           // rows m0, m0+8
    const int ijA = (i0 + (m0 >> 3)) * 32 + j0 + (m0 & 7);
    const int mB = m0 + 8;
    const int ijB = (i0 + (mB >> 3)) * 32 + j0 + (mB & 7);

    float* outb = out + (size_t)bidx * 65536;
#pragma unroll
    for (int ni = 0; ni < 8; ni++) {
        int f = ni*8 + kq;
        float2 bias = *(const float2*)(fc_b + f);
        *(float2*)&outb[(size_t)ijA * 64 + f] =
            make_float2(acc[ni][0] + bias.x, acc[ni][1] + bias.y);
        *(float2*)&outb[(size_t)ijB * 64 + f] =
            make_float2(acc[ni][2] + bias.x, acc[ni][3] + bias.y);
    }
}

// ---------------------------------------------------------------------------
extern "C" void kernel_launch(void* const* d_in, const int* in_sizes, int n_in,
                              void* d_out, int out_size) {
    const float* X       = (const float*)d_in[0];
    const float* centers = (const float*)d_in[2];
    const float* spreads = (const float*)d_in[3];
    const float* fc_w    = (const float*)d_in[4];
    const float* fc_b    = (const float*)d_in[5];
    float* out = (float*)d_out;

    cudaFuncSetAttribute(k_mid, cudaFuncAttributeMaxDynamicSharedMemorySize, MID_SMEM);
    cudaFuncSetAttribute(k_gemm, cudaFuncAttributeMaxDynamicSharedMemorySize, GSMEM);

    k_prep<<<1160, 256>>>(X, fc_w, centers, spreads);
    k_mid<<<1280, 256, MID_SMEM>>>();
    dim3 gg(8, 32);
    k_gemm<<<gg, 256, GSMEM>>>(fc_b, out);
}